// round 2
// baseline (speedup 1.0000x reference)
#include <cuda_runtime.h>
#include <math.h>

#define TOK_TOTAL 57344   // B*N = 8*7168
#define U_TOK     49152
#define N_TOK     7168

typedef unsigned long long u64;

// scratch: z1 = LN1(attention output), [B*N, 64] fp32
__device__ float g_z1[TOK_TOTAL * 64];

// ---------------- packed f32x2 helpers (sm_100+) ----------------
__device__ __forceinline__ u64 pk2(float x, float y) {
    u64 r; asm("mov.b64 %0, {%1,%2};" : "=l"(r) : "f"(x), "f"(y)); return r;
}
__device__ __forceinline__ float2 up2(u64 v) {
    float2 f; asm("mov.b64 {%0,%1}, %2;" : "=f"(f.x), "=f"(f.y) : "l"(v)); return f;
}
__device__ __forceinline__ u64 ffma2(u64 a, u64 b, u64 c) {
    u64 d; asm("fma.rn.f32x2 %0, %1, %2, %3;" : "=l"(d) : "l"(a), "l"(b), "l"(c)); return d;
}
__device__ __forceinline__ u64 fmul2(u64 a, u64 b) {
    u64 d; asm("mul.rn.f32x2 %0, %1, %2;" : "=l"(d) : "l"(a), "l"(b)); return d;
}

__device__ __forceinline__ float warp_sum(float v) {
    #pragma unroll
    for (int off = 16; off >= 1; off >>= 1)
        v += __shfl_xor_sync(0xffffffffu, v, off);
    return v;
}

// ================= Kernel 1: attention + LN1 =================
// per warp: one x-token. channel pair per lane: c = 2*lane, 2*lane+1.
// group of a lane = (2*lane)>>4 = lane>>3 -> 8-lane shfl reductions.

template <int NCH>
__device__ __forceinline__ void do_chunk(
    const float* __restrict__ ub,  // chunk base: NCH contiguous u tokens * 64
    float* su, int lane, int c,
    u64 bk2, u64 bv2,
    const float* sWk, const float* sWv,
    float2 qf, float& m, float& s, u64& o2)
{
    // stage NCH*64 floats (contiguous in gmem)
    const float4* up4 = (const float4*)ub;
    #pragma unroll
    for (int i = 0; i < (NCH * 16) / 32; i++)
        ((float4*)su)[lane + 32 * i] = up4[lane + 32 * i];
    __syncwarp();

    u64 kk[NCH], vv[NCH];
    #pragma unroll
    for (int t = 0; t < NCH; t++) { kk[t] = bk2; vv[t] = bv2; }

    #pragma unroll 4
    for (int d = 0; d < 64; d += 2) {
        u64 wk0 = *(const u64*)(sWk + d * 64 + c);
        u64 wk1 = *(const u64*)(sWk + (d + 1) * 64 + c);
        u64 wv0 = *(const u64*)(sWv + d * 64 + c);
        u64 wv1 = *(const u64*)(sWv + (d + 1) * 64 + c);
        #pragma unroll
        for (int t = 0; t < NCH; t++) {
            float2 uv = *(const float2*)(su + t * 64 + d);
            u64 u0 = pk2(uv.x, uv.x);
            u64 u1 = pk2(uv.y, uv.y);
            kk[t] = ffma2(wk0, u0, kk[t]);
            vv[t] = ffma2(wv0, u0, vv[t]);
            kk[t] = ffma2(wk1, u1, kk[t]);
            vv[t] = ffma2(wv1, u1, vv[t]);
        }
    }
    __syncwarp();   // all su reads done before caller restages

    // group logits: dot over the 16 channels of this lane's group
    float lg[NCH];
    #pragma unroll
    for (int t = 0; t < NCH; t++) {
        float2 kf = up2(kk[t]);
        float p = kf.x * qf.x + kf.y * qf.y;
        p += __shfl_xor_sync(0xffffffffu, p, 4);
        p += __shfl_xor_sync(0xffffffffu, p, 2);
        p += __shfl_xor_sync(0xffffffffu, p, 1);
        lg[t] = p * 0.125f;   // 1/sqrt(64)
    }
    // online softmax update
    float cm = lg[0];
    #pragma unroll
    for (int t = 1; t < NCH; t++) cm = fmaxf(cm, lg[t]);
    float nm = fmaxf(m, cm);
    float corr = __expf(m - nm);
    s *= corr;
    o2 = fmul2(o2, pk2(corr, corr));
    #pragma unroll
    for (int t = 0; t < NCH; t++) {
        float w = __expf(lg[t] - nm);
        s += w;
        o2 = ffma2(vv[t], pk2(w, w), o2);
    }
    m = nm;
}

__global__ void __launch_bounds__(256, 3) attn_kernel(
    const float* __restrict__ u, const float* __restrict__ x,
    const float* __restrict__ Wk, const float* __restrict__ bk,
    const float* __restrict__ Wq, const float* __restrict__ bq,
    const float* __restrict__ Wv, const float* __restrict__ bv,
    const float* __restrict__ g1, const float* __restrict__ be1)
{
    extern __shared__ float sm1[];
    float* sWk = sm1;              // 4096
    float* sWq = sm1 + 4096;       // 4096
    float* sWv = sm1 + 8192;       // 4096
    float* sB  = sm1 + 12288;      // bk[0:64) bq[64:128) bv[128:192) g1[192:256) be1[256:320)
    float* sStage = sm1 + 12608;   // 8 warps * (64 + 512)

    int tid = threadIdx.x;
    for (int i = tid; i < 4096; i += 256) { sWk[i] = Wk[i]; sWq[i] = Wq[i]; sWv[i] = Wv[i]; }
    if (tid < 64) {
        sB[tid]       = bk[tid];
        sB[64 + tid]  = bq[tid];
        sB[128 + tid] = bv[tid];
        sB[192 + tid] = g1[tid];
        sB[256 + tid] = be1[tid];
    }
    __syncthreads();

    int warp = tid >> 5, lane = tid & 31;
    int c = 2 * lane;
    float* sx = sStage + warp * 576;
    float* su = sx + 64;

    u64 bk2 = *(const u64*)&sB[c];
    u64 bq2 = *(const u64*)&sB[64 + c];
    u64 bv2 = *(const u64*)&sB[128 + c];
    float gg0 = sB[192 + c], gg1 = sB[192 + c + 1];
    float bb0 = sB[256 + c], bb1 = sB[256 + c + 1];

    int wg = blockIdx.x * 8 + warp;
    int nwarps = gridDim.x * 8;

    for (int tok = wg; tok < TOK_TOTAL; tok += nwarps) {
        int b = tok / N_TOK;
        int n = tok - b * N_TOK;
        int to, off0, off1, nl;
        if (n < 4096)      { to = 4;  off0 = 0;     off1 = 24576; nl = n; }
        else if (n < 6144) { to = 8;  off0 = 8192;  off1 = 32768; nl = n - 4096; }
        else               { to = 16; off0 = 16384; off1 = 40960; nl = n - 6144; }
        int f = nl * to;
        int g = (f < 8192) ? (off0 + f) : (off1 + f - 8192);
        const float* ub = u + ((size_t)b * U_TOK + g) * 64;
        const float* xb = x + (size_t)tok * 64;

        // stage x token
        sx[lane] = xb[lane];
        sx[lane + 32] = xb[lane + 32];
        __syncwarp();

        // q projection (channel pair c, c+1)
        u64 q2 = bq2;
        #pragma unroll 8
        for (int d = 0; d < 64; d += 2) {
            float2 xv = *(const float2*)&sx[d];
            q2 = ffma2(*(const u64*)&sWq[d * 64 + c], pk2(xv.x, xv.x), q2);
            q2 = ffma2(*(const u64*)&sWq[(d + 1) * 64 + c], pk2(xv.y, xv.y), q2);
        }
        float2 qf = up2(q2);

        float m = -1e30f, s = 0.0f;
        u64 o2 = pk2(0.0f, 0.0f);

        if (to == 4) {
            do_chunk<4>(ub, su, lane, c, bk2, bv2, sWk, sWv, qf, m, s, o2);
        } else {
            for (int cc = 0; cc < to; cc += 8)
                do_chunk<8>(ub + (size_t)cc * 64, su, lane, c, bk2, bv2, sWk, sWv, qf, m, s, o2);
        }

        float2 of = up2(o2);
        float inv = 1.0f / s;
        of.x *= inv; of.y *= inv;

        // LN1 over 64 channels (warp-wide)
        float mean = warp_sum(of.x + of.y) * (1.0f / 64.0f);
        float d0 = of.x - mean, d1 = of.y - mean;
        float var = warp_sum(d0 * d0 + d1 * d1) * (1.0f / 64.0f);
        float r = rsqrtf(var + 1e-5f);
        float2 y;
        y.x = d0 * r * gg0 + bb0;
        y.y = d1 * r * gg1 + bb1;
        *(float2*)&g_z1[(size_t)tok * 64 + c] = y;
    }
}

// ================= Kernel 2: MLP + LN2 + shortcut =================
// per warp: 4 tokens. matvec1 channels per lane: 64*k + 2*lane (+1), k=0..3.

__device__ __forceinline__ float gelu_exact(float v) {
    return 0.5f * v * (1.0f + erff(v * 0.70710678118654752f));
}

__global__ void __launch_bounds__(512, 1) mlp_kernel(
    const float* __restrict__ x,
    const float* __restrict__ Wm1, const float* __restrict__ bm1,
    const float* __restrict__ Wm2, const float* __restrict__ bm2,
    const float* __restrict__ g2,  const float* __restrict__ be2,
    const float* __restrict__ Ws,  const float* __restrict__ bs,
    float* __restrict__ out)
{
    extern __shared__ float sm2[];
    float* sW1 = sm2;               // 16384  [d][256]
    float* sW2 = sm2 + 16384;       // 16384  [c][64]
    float* sWs = sm2 + 32768;       // 4096   [d][64]
    float* sB  = sm2 + 36864;       // bm1[0:256) bm2[256:320) g2[320:384) be2[384:448) bs[448:512)
    float* sStage = sm2 + 37376;    // 16 warps * 4 tok * 256

    int tid = threadIdx.x;
    for (int i = tid; i < 16384; i += 512) { sW1[i] = Wm1[i]; sW2[i] = Wm2[i]; }
    for (int i = tid; i < 4096; i += 512) sWs[i] = Ws[i];
    if (tid < 256) sB[tid] = bm1[tid];
    if (tid < 64) {
        sB[256 + tid] = bm2[tid];
        sB[320 + tid] = g2[tid];
        sB[384 + tid] = be2[tid];
        sB[448 + tid] = bs[tid];
    }
    __syncthreads();

    int warp = tid >> 5, lane = tid & 31;
    int l2 = 2 * lane;
    float* slab = sStage + warp * 1024;

    u64 bm2p = *(const u64*)&sB[256 + l2];
    u64 bsp  = *(const u64*)&sB[448 + l2];
    float gg0 = sB[320 + l2], gg1 = sB[320 + l2 + 1];
    float bb0 = sB[384 + l2], bb1 = sB[384 + l2 + 1];

    int wg = blockIdx.x * 16 + warp;
    int nw = gridDim.x * 16;

    for (int grp = wg; grp < TOK_TOTAL / 4; grp += nw) {
        int tok0 = grp * 4;

        // stage z1 (4 tokens) into slab[t][0:64)
        #pragma unroll
        for (int t = 0; t < 4; t++) {
            slab[t * 256 + lane]      = g_z1[(size_t)(tok0 + t) * 64 + lane];
            slab[t * 256 + lane + 32] = g_z1[(size_t)(tok0 + t) * 64 + lane + 32];
        }
        __syncwarp();

        // ---- matvec1: 64 -> 256 ----
        u64 h[4][4];
        #pragma unroll
        for (int k = 0; k < 4; k++) {
            u64 bm = *(const u64*)&sB[64 * k + l2];
            #pragma unroll
            for (int t = 0; t < 4; t++) h[k][t] = bm;
        }
        #pragma unroll 2
        for (int d = 0; d < 64; d += 2) {
            u64 w0[4], w1[4];
            #pragma unroll
            for (int k = 0; k < 4; k++) {
                w0[k] = *(const u64*)&sW1[d * 256 + 64 * k + l2];
                w1[k] = *(const u64*)&sW1[(d + 1) * 256 + 64 * k + l2];
            }
            #pragma unroll
            for (int t = 0; t < 4; t++) {
                float2 zv = *(const float2*)&slab[t * 256 + d];
                u64 z0 = pk2(zv.x, zv.x);
                u64 z1 = pk2(zv.y, zv.y);
                #pragma unroll
                for (int k = 0; k < 4; k++) {
                    h[k][t] = ffma2(w0[k], z0, h[k][t]);
                    h[k][t] = ffma2(w1[k], z1, h[k][t]);
                }
            }
        }
        __syncwarp();   // all z reads done before overwrite

        // ---- gelu + stage h to slab[t][0:256) ----
        #pragma unroll
        for (int t = 0; t < 4; t++) {
            #pragma unroll
            for (int k = 0; k < 4; k++) {
                float2 hv = up2(h[k][t]);
                hv.x = gelu_exact(hv.x);
                hv.y = gelu_exact(hv.y);
                *(u64*)&slab[t * 256 + 64 * k + l2] = pk2(hv.x, hv.y);
            }
        }
        __syncwarp();

        // ---- matvec2: 256 -> 64 ----
        u64 o[4];
        #pragma unroll
        for (int t = 0; t < 4; t++) o[t] = bm2p;
        #pragma unroll 4
        for (int cb = 0; cb < 256; cb += 2) {
            u64 wA = *(const u64*)&sW2[cb * 64 + l2];
            u64 wB = *(const u64*)&sW2[(cb + 1) * 64 + l2];
            #pragma unroll
            for (int t = 0; t < 4; t++) {
                float2 hv = *(const float2*)&slab[t * 256 + cb];
                o[t] = ffma2(wA, pk2(hv.x, hv.x), o[t]);
                o[t] = ffma2(wB, pk2(hv.y, hv.y), o[t]);
            }
        }
        __syncwarp();

        // ---- stage x, shortcut matvec ----
        #pragma unroll
        for (int t = 0; t < 4; t++) {
            slab[t * 256 + lane]      = x[(size_t)(tok0 + t) * 64 + lane];
            slab[t * 256 + lane + 32] = x[(size_t)(tok0 + t) * 64 + lane + 32];
        }
        __syncwarp();
        u64 sc[4];
        #pragma unroll
        for (int t = 0; t < 4; t++) sc[t] = bsp;
        #pragma unroll 4
        for (int d = 0; d < 64; d += 2) {
            u64 wA = *(const u64*)&sWs[d * 64 + l2];
            u64 wB = *(const u64*)&sWs[(d + 1) * 64 + l2];
            #pragma unroll
            for (int t = 0; t < 4; t++) {
                float2 xv = *(const float2*)&slab[t * 256 + d];
                sc[t] = ffma2(wA, pk2(xv.x, xv.x), sc[t]);
                sc[t] = ffma2(wB, pk2(xv.y, xv.y), sc[t]);
            }
        }
        __syncwarp();

        // ---- LN2 + shortcut + write ----
        #pragma unroll
        for (int t = 0; t < 4; t++) {
            float2 ov = up2(o[t]);
            float mean = warp_sum(ov.x + ov.y) * (1.0f / 64.0f);
            float d0 = ov.x - mean, d1 = ov.y - mean;
            float var = warp_sum(d0 * d0 + d1 * d1) * (1.0f / 64.0f);
            float r = rsqrtf(var + 1e-5f);
            float2 scv = up2(sc[t]);
            float2 y;
            y.x = d0 * r * gg0 + bb0 + scv.x;
            y.y = d1 * r * gg1 + bb1 + scv.y;
            *(float2*)&out[(size_t)(tok0 + t) * 64 + l2] = y;
        }
    }
}

// ================= launch =================
extern "C" void kernel_launch(void* const* d_in, const int* in_sizes, int n_in,
                              void* d_out, int out_size)
{
    const float* u   = (const float*)d_in[0];
    const float* x   = (const float*)d_in[1];
    const float* Wk  = (const float*)d_in[2];
    const float* bk  = (const float*)d_in[3];
    const float* Wq  = (const float*)d_in[4];
    const float* bq  = (const float*)d_in[5];
    const float* Wv  = (const float*)d_in[6];
    const float* bv  = (const float*)d_in[7];
    const float* g1  = (const float*)d_in[8];
    const float* be1 = (const float*)d_in[9];
    const float* Wm1 = (const float*)d_in[10];
    const float* bm1 = (const float*)d_in[11];
    const float* Wm2 = (const float*)d_in[12];
    const float* bm2 = (const float*)d_in[13];
    const float* g2  = (const float*)d_in[14];
    const float* be2 = (const float*)d_in[15];
    const float* Ws  = (const float*)d_in[16];
    const float* bs  = (const float*)d_in[17];
    float* out = (float*)d_out;

    const int smem1 = 17216 * 4;   // 68864 B
    const int smem2 = 53760 * 4;   // 215040 B
    cudaFuncSetAttribute(attn_kernel, cudaFuncAttributeMaxDynamicSharedMemorySize, smem1);
    cudaFuncSetAttribute(mlp_kernel,  cudaFuncAttributeMaxDynamicSharedMemorySize, smem2);

    attn_kernel<<<444, 256, smem1>>>(u, x, Wk, bk, Wq, bq, Wv, bv, g1, be1);
    mlp_kernel<<<148, 512, smem2>>>(x, Wm1, bm1, Wm2, bm2, g2, be2, Ws, bs, out);
}

// round 3
// speedup vs baseline: 1.1848x; 1.1848x over previous
#include <cuda_runtime.h>
#include <math.h>

#define TOK_TOTAL 57344   // B*N = 8*7168
#define U_TOK     49152
#define N_TOK     7168

typedef unsigned long long u64;

// scratch: z1 = LN1(attention output), [B*N, 64] fp32
__device__ float g_z1[TOK_TOTAL * 64];

// ---------------- packed f32x2 helpers (sm_100+) ----------------
__device__ __forceinline__ u64 pk2(float x, float y) {
    u64 r; asm("mov.b64 %0, {%1,%2};" : "=l"(r) : "f"(x), "f"(y)); return r;
}
__device__ __forceinline__ float2 up2(u64 v) {
    float2 f; asm("mov.b64 {%0,%1}, %2;" : "=f"(f.x), "=f"(f.y) : "l"(v)); return f;
}
__device__ __forceinline__ u64 ffma2(u64 a, u64 b, u64 c) {
    u64 d; asm("fma.rn.f32x2 %0, %1, %2, %3;" : "=l"(d) : "l"(a), "l"(b), "l"(c)); return d;
}
__device__ __forceinline__ u64 fadd2(u64 a, u64 b) {
    u64 d; asm("add.rn.f32x2 %0, %1, %2;" : "=l"(d) : "l"(a), "l"(b)); return d;
}

__device__ __forceinline__ float warp_sum(float v) {
    #pragma unroll
    for (int off = 16; off >= 1; off >>= 1)
        v += __shfl_xor_sync(0xffffffffu, v, off);
    return v;
}

// ================= Kernel 1: factored attention + LN1 =================
// per warp: one x-token.
//   logit_{t,g} = u_t . wkq_g + bkq_g,   wkq_g = Wk @ q_g  (per-token precompute)
//   out_g       = (sum_t a_tg u_t) @ Wv + bv
// lane channel pair: c = 2*lane. out-group of lane: lane>>3.

#define WARP_SLAB 1440   // floats per warp slab
// slab layout: su[0:1088) (16 rows x 68), swkq[1088:1352) (4 x 66),
//              sq/sa[1352:1416) (64), sbkq[1416:1420)

__global__ void __launch_bounds__(256, 2) attn_kernel(
    const float* __restrict__ u, const float* __restrict__ x,
    const float* __restrict__ Wk, const float* __restrict__ bk,
    const float* __restrict__ Wq, const float* __restrict__ bq,
    const float* __restrict__ Wv, const float* __restrict__ bv,
    const float* __restrict__ g1, const float* __restrict__ be1)
{
    extern __shared__ float sm1[];
    float* sWq  = sm1;              // 4096  [d][c]
    float* sWkT = sm1 + 4096;       // 4096  [c][d]  (transposed Wk)
    float* sWv  = sm1 + 8192;       // 4096  [d][c]
    float* sB   = sm1 + 12288;      // bk[0:64) bq[64:128) bv[128:192) g1[192:256) be1[256:320)
    float* sSlab = sm1 + 12608;     // 8 warps * WARP_SLAB

    int tid = threadIdx.x;
    for (int i = tid; i < 4096; i += 256) {
        sWq[i] = Wq[i];
        sWv[i] = Wv[i];
        int cc = i >> 6, dd = i & 63;
        sWkT[i] = Wk[dd * 64 + cc];
    }
    if (tid < 64) {
        sB[tid]       = bk[tid];
        sB[64 + tid]  = bq[tid];
        sB[128 + tid] = bv[tid];
        sB[192 + tid] = g1[tid];
        sB[256 + tid] = be1[tid];
    }
    __syncthreads();

    int warp = tid >> 5, lane = tid & 31;
    int c = 2 * lane;
    float* su   = sSlab + warp * WARP_SLAB;
    float* swkq = su + 1088;
    float* sq   = su + 1352;   // aliased as sa after q is consumed
    float* sa   = sq;
    float* sbkq = su + 1416;
    float* sr   = su;          // r[g][d] overlaid on su after u consumed

    float bk0 = sB[c], bk1 = sB[c + 1];
    u64 bq2 = *(const u64*)&sB[64 + c];
    u64 bv2 = *(const u64*)&sB[128 + c];
    float gg0 = sB[192 + c], gg1 = sB[192 + c + 1];
    float bb0 = sB[256 + c], bb1 = sB[256 + c + 1];

    int tt = lane >> 2, glog = lane & 3;   // logit-phase mapping: lane -> (token tt, group glog)
    int gout = lane >> 3;                  // out-projection group of this lane's channel pair

    int wg = blockIdx.x * 8 + warp;
    int nwarps = gridDim.x * 8;

    for (int tok = wg; tok < TOK_TOTAL; tok += nwarps) {
        int b = tok / N_TOK;
        int n = tok - b * N_TOK;
        int to, off0, off1, nl;
        if (n < 4096)      { to = 4;  off0 = 0;     off1 = 24576; nl = n; }
        else if (n < 6144) { to = 8;  off0 = 8192;  off1 = 32768; nl = n - 4096; }
        else               { to = 16; off0 = 16384; off1 = 40960; nl = n - 6144; }
        int f = nl * to;
        int g = (f < 8192) ? (off0 + f) : (off1 + f - 8192);
        const float* ub = u + ((size_t)b * U_TOK + g) * 64;
        const float* xb = x + (size_t)tok * 64;

        // ---- stage x into su[0:64) (temp), q projection ----
        su[lane] = xb[lane];
        su[lane + 32] = xb[lane + 32];
        __syncwarp();
        u64 qa = bq2, qb = pk2(0.f, 0.f);
        #pragma unroll 8
        for (int d = 0; d < 64; d += 4) {
            float2 x0 = *(const float2*)&su[d];
            float2 x1 = *(const float2*)&su[d + 2];
            qa = ffma2(*(const u64*)&sWq[d * 64 + c],       pk2(x0.x, x0.x), qa);
            qb = ffma2(*(const u64*)&sWq[(d + 1) * 64 + c], pk2(x0.y, x0.y), qb);
            qa = ffma2(*(const u64*)&sWq[(d + 2) * 64 + c], pk2(x1.x, x1.x), qa);
            qb = ffma2(*(const u64*)&sWq[(d + 3) * 64 + c], pk2(x1.y, x1.y), qb);
        }
        u64 q2 = fadd2(qa, qb);
        float2 qf = up2(q2);
        __syncwarp();                    // x reads done before sq write (sq separate anyway)
        *(u64*)&sq[c] = q2;              // STS.64 (sq region, not su)

        // bkq_g = sum_{ch in g} bk[ch]*q[ch]
        float p = bk0 * qf.x + bk1 * qf.y;
        p += __shfl_xor_sync(0xffffffffu, p, 1);
        p += __shfl_xor_sync(0xffffffffu, p, 2);
        p += __shfl_xor_sync(0xffffffffu, p, 4);
        if ((lane & 7) == 0) sbkq[lane >> 3] = p;
        __syncwarp();

        // ---- wkq_g[d-pair of this lane] ----
        u64 wkql[4];
        #pragma unroll
        for (int gi = 0; gi < 4; gi++) {
            u64 a0 = pk2(0.f, 0.f), a1 = pk2(0.f, 0.f);
            #pragma unroll
            for (int c0 = 16 * gi; c0 < 16 * gi + 16; c0 += 2) {
                float2 qp = *(const float2*)&sq[c0];
                a0 = ffma2(*(const u64*)&sWkT[c0 * 64 + c],       pk2(qp.x, qp.x), a0);
                a1 = ffma2(*(const u64*)&sWkT[(c0 + 1) * 64 + c], pk2(qp.y, qp.y), a1);
            }
            wkql[gi] = fadd2(a0, a1);
        }
        #pragma unroll
        for (int gi = 0; gi < 4; gi++)
            *(u64*)&swkq[gi * 66 + c] = wkql[gi];
        __syncwarp();

        // ---- stage u (to tokens, padded rows of 68) ----
        const float4* up4 = (const float4*)ub;
        for (int i = lane; i < to * 16; i += 32) {
            float4 v = up4[i];
            int t = i >> 4, dd = (i & 15) << 2;
            *(float4*)&su[t * 68 + dd] = v;
        }
        __syncwarp();

        // ---- logits: lane computes (tt, glog); up to 2 rounds for to=16 ----
        int tval = (to < 8) ? to : 8;
        float lg0 = -1e30f, lg1 = -1e30f;
        float bqg = sbkq[glog];
        if (tt < tval) {
            u64 a0 = pk2(0.f, 0.f), a1 = pk2(0.f, 0.f);
            #pragma unroll 8
            for (int d = 0; d < 64; d += 4) {
                a0 = ffma2(*(const u64*)&su[tt * 68 + d],     *(const u64*)&swkq[glog * 66 + d],     a0);
                a1 = ffma2(*(const u64*)&su[tt * 68 + d + 2], *(const u64*)&swkq[glog * 66 + d + 2], a1);
            }
            float2 s2 = up2(fadd2(a0, a1));
            lg0 = (s2.x + s2.y + bqg) * 0.125f;
        }
        if (to == 16) {
            int t = tt + 8;
            u64 a0 = pk2(0.f, 0.f), a1 = pk2(0.f, 0.f);
            #pragma unroll 8
            for (int d = 0; d < 64; d += 4) {
                a0 = ffma2(*(const u64*)&su[t * 68 + d],     *(const u64*)&swkq[glog * 66 + d],     a0);
                a1 = ffma2(*(const u64*)&su[t * 68 + d + 2], *(const u64*)&swkq[glog * 66 + d + 2], a1);
            }
            float2 s2 = up2(fadd2(a0, a1));
            lg1 = (s2.x + s2.y + bqg) * 0.125f;
        }

        // ---- softmax over t (lanes with same glog: xor 4,8,16) ----
        float m = fmaxf(lg0, lg1);
        m = fmaxf(m, __shfl_xor_sync(0xffffffffu, m, 4));
        m = fmaxf(m, __shfl_xor_sync(0xffffffffu, m, 8));
        m = fmaxf(m, __shfl_xor_sync(0xffffffffu, m, 16));
        float w0 = __expf(lg0 - m);
        float w1 = __expf(lg1 - m);
        float s = w0 + w1;
        s += __shfl_xor_sync(0xffffffffu, s, 4);
        s += __shfl_xor_sync(0xffffffffu, s, 8);
        s += __shfl_xor_sync(0xffffffffu, s, 16);
        float inv = 1.0f / s;
        if (tt < tval) sa[lane] = w0 * inv;          // sa[tt*4+glog] == sa[lane]
        if (to == 16)  sa[lane + 32] = w1 * inv;
        __syncwarp();

        // ---- r_g[d-pair] = sum_t a_tg * u_t[d-pair] ----
        u64 r0 = pk2(0.f, 0.f), r1 = pk2(0.f, 0.f), r2 = pk2(0.f, 0.f), r3 = pk2(0.f, 0.f);
        for (int t = 0; t < to; t++) {
            float4 a4 = *(const float4*)&sa[t * 4];
            u64 uu = *(const u64*)&su[t * 68 + c];
            r0 = ffma2(uu, pk2(a4.x, a4.x), r0);
            r1 = ffma2(uu, pk2(a4.y, a4.y), r1);
            r2 = ffma2(uu, pk2(a4.z, a4.z), r2);
            r3 = ffma2(uu, pk2(a4.w, a4.w), r3);
        }
        __syncwarp();                 // all su reads done
        *(u64*)&sr[0 * 66 + c] = r0;  // overlay on su
        *(u64*)&sr[1 * 66 + c] = r1;
        *(u64*)&sr[2 * 66 + c] = r2;
        *(u64*)&sr[3 * 66 + c] = r3;
        __syncwarp();

        // ---- out projection: out[c..c+1] = r_{gout} @ Wv[:, c..c+1] + bv ----
        u64 oa = bv2, ob = pk2(0.f, 0.f);
        #pragma unroll 8
        for (int d = 0; d < 64; d += 4) {
            float2 rp0 = *(const float2*)&sr[gout * 66 + d];
            float2 rp1 = *(const float2*)&sr[gout * 66 + d + 2];
            oa = ffma2(*(const u64*)&sWv[d * 64 + c],       pk2(rp0.x, rp0.x), oa);
            ob = ffma2(*(const u64*)&sWv[(d + 1) * 64 + c], pk2(rp0.y, rp0.y), ob);
            oa = ffma2(*(const u64*)&sWv[(d + 2) * 64 + c], pk2(rp1.x, rp1.x), oa);
            ob = ffma2(*(const u64*)&sWv[(d + 3) * 64 + c], pk2(rp1.y, rp1.y), ob);
        }
        float2 of = up2(fadd2(oa, ob));
        __syncwarp();                 // sr reads done before next iter's su staging

        // ---- LN1 + store ----
        float mean = warp_sum(of.x + of.y) * (1.0f / 64.0f);
        float d0 = of.x - mean, d1 = of.y - mean;
        float var = warp_sum(d0 * d0 + d1 * d1) * (1.0f / 64.0f);
        float r = rsqrtf(var + 1e-5f);
        float2 y;
        y.x = d0 * r * gg0 + bb0;
        y.y = d1 * r * gg1 + bb1;
        *(float2*)&g_z1[(size_t)tok * 64 + c] = y;
    }
}

// ================= Kernel 2: MLP + LN2 + shortcut (unchanged) =================

__device__ __forceinline__ float gelu_exact(float v) {
    return 0.5f * v * (1.0f + erff(v * 0.70710678118654752f));
}

__global__ void __launch_bounds__(512, 1) mlp_kernel(
    const float* __restrict__ x,
    const float* __restrict__ Wm1, const float* __restrict__ bm1,
    const float* __restrict__ Wm2, const float* __restrict__ bm2,
    const float* __restrict__ g2,  const float* __restrict__ be2,
    const float* __restrict__ Ws,  const float* __restrict__ bs,
    float* __restrict__ out)
{
    extern __shared__ float sm2[];
    float* sW1 = sm2;               // 16384  [d][256]
    float* sW2 = sm2 + 16384;       // 16384  [c][64]
    float* sWs = sm2 + 32768;       // 4096   [d][64]
    float* sB  = sm2 + 36864;
    float* sStage = sm2 + 37376;    // 16 warps * 1024

    int tid = threadIdx.x;
    for (int i = tid; i < 16384; i += 512) { sW1[i] = Wm1[i]; sW2[i] = Wm2[i]; }
    for (int i = tid; i < 4096; i += 512) sWs[i] = Ws[i];
    if (tid < 256) sB[tid] = bm1[tid];
    if (tid < 64) {
        sB[256 + tid] = bm2[tid];
        sB[320 + tid] = g2[tid];
        sB[384 + tid] = be2[tid];
        sB[448 + tid] = bs[tid];
    }
    __syncthreads();

    int warp = tid >> 5, lane = tid & 31;
    int l2 = 2 * lane;
    float* slab = sStage + warp * 1024;

    u64 bm2p = *(const u64*)&sB[256 + l2];
    u64 bsp  = *(const u64*)&sB[448 + l2];
    float gg0 = sB[320 + l2], gg1 = sB[320 + l2 + 1];
    float bb0 = sB[384 + l2], bb1 = sB[384 + l2 + 1];

    int wg = blockIdx.x * 16 + warp;
    int nw = gridDim.x * 16;

    for (int grp = wg; grp < TOK_TOTAL / 4; grp += nw) {
        int tok0 = grp * 4;

        #pragma unroll
        for (int t = 0; t < 4; t++) {
            slab[t * 256 + lane]      = g_z1[(size_t)(tok0 + t) * 64 + lane];
            slab[t * 256 + lane + 32] = g_z1[(size_t)(tok0 + t) * 64 + lane + 32];
        }
        __syncwarp();

        u64 h[4][4];
        #pragma unroll
        for (int k = 0; k < 4; k++) {
            u64 bm = *(const u64*)&sB[64 * k + l2];
            #pragma unroll
            for (int t = 0; t < 4; t++) h[k][t] = bm;
        }
        #pragma unroll 2
        for (int d = 0; d < 64; d += 2) {
            u64 w0[4], w1[4];
            #pragma unroll
            for (int k = 0; k < 4; k++) {
                w0[k] = *(const u64*)&sW1[d * 256 + 64 * k + l2];
                w1[k] = *(const u64*)&sW1[(d + 1) * 256 + 64 * k + l2];
            }
            #pragma unroll
            for (int t = 0; t < 4; t++) {
                float2 zv = *(const float2*)&slab[t * 256 + d];
                u64 z0 = pk2(zv.x, zv.x);
                u64 z1 = pk2(zv.y, zv.y);
                #pragma unroll
                for (int k = 0; k < 4; k++) {
                    h[k][t] = ffma2(w0[k], z0, h[k][t]);
                    h[k][t] = ffma2(w1[k], z1, h[k][t]);
                }
            }
        }
        __syncwarp();

        #pragma unroll
        for (int t = 0; t < 4; t++) {
            #pragma unroll
            for (int k = 0; k < 4; k++) {
                float2 hv = up2(h[k][t]);
                hv.x = gelu_exact(hv.x);
                hv.y = gelu_exact(hv.y);
                *(u64*)&slab[t * 256 + 64 * k + l2] = pk2(hv.x, hv.y);
            }
        }
        __syncwarp();

        u64 o[4];
        #pragma unroll
        for (int t = 0; t < 4; t++) o[t] = bm2p;
        #pragma unroll 4
        for (int cb = 0; cb < 256; cb += 2) {
            u64 wA = *(const u64*)&sW2[cb * 64 + l2];
            u64 wB = *(const u64*)&sW2[(cb + 1) * 64 + l2];
            #pragma unroll
            for (int t = 0; t < 4; t++) {
                float2 hv = *(const float2*)&slab[t * 256 + cb];
                o[t] = ffma2(wA, pk2(hv.x, hv.x), o[t]);
                o[t] = ffma2(wB, pk2(hv.y, hv.y), o[t]);
            }
        }
        __syncwarp();

        #pragma unroll
        for (int t = 0; t < 4; t++) {
            slab[t * 256 + lane]      = x[(size_t)(tok0 + t) * 64 + lane];
            slab[t * 256 + lane + 32] = x[(size_t)(tok0 + t) * 64 + lane + 32];
        }
        __syncwarp();
        u64 sc[4];
        #pragma unroll
        for (int t = 0; t < 4; t++) sc[t] = bsp;
        #pragma unroll 4
        for (int d = 0; d < 64; d += 2) {
            u64 wA = *(const u64*)&sWs[d * 64 + l2];
            u64 wB = *(const u64*)&sWs[(d + 1) * 64 + l2];
            #pragma unroll
            for (int t = 0; t < 4; t++) {
                float2 xv = *(const float2*)&slab[t * 256 + d];
                sc[t] = ffma2(wA, pk2(xv.x, xv.x), sc[t]);
                sc[t] = ffma2(wB, pk2(xv.y, xv.y), sc[t]);
            }
        }
        __syncwarp();

        #pragma unroll
        for (int t = 0; t < 4; t++) {
            float2 ov = up2(o[t]);
            float mean = warp_sum(ov.x + ov.y) * (1.0f / 64.0f);
            float d0 = ov.x - mean, d1 = ov.y - mean;
            float var = warp_sum(d0 * d0 + d1 * d1) * (1.0f / 64.0f);
            float r = rsqrtf(var + 1e-5f);
            float2 scv = up2(sc[t]);
            float2 y;
            y.x = d0 * r * gg0 + bb0 + scv.x;
            y.y = d1 * r * gg1 + bb1 + scv.y;
            *(float2*)&out[(size_t)(tok0 + t) * 64 + l2] = y;
        }
    }
}

// ================= launch =================
extern "C" void kernel_launch(void* const* d_in, const int* in_sizes, int n_in,
                              void* d_out, int out_size)
{
    const float* u   = (const float*)d_in[0];
    const float* x   = (const float*)d_in[1];
    const float* Wk  = (const float*)d_in[2];
    const float* bk  = (const float*)d_in[3];
    const float* Wq  = (const float*)d_in[4];
    const float* bq  = (const float*)d_in[5];
    const float* Wv  = (const float*)d_in[6];
    const float* bv  = (const float*)d_in[7];
    const float* g1  = (const float*)d_in[8];
    const float* be1 = (const float*)d_in[9];
    const float* Wm1 = (const float*)d_in[10];
    const float* bm1 = (const float*)d_in[11];
    const float* Wm2 = (const float*)d_in[12];
    const float* bm2 = (const float*)d_in[13];
    const float* g2  = (const float*)d_in[14];
    const float* be2 = (const float*)d_in[15];
    const float* Ws  = (const float*)d_in[16];
    const float* bs  = (const float*)d_in[17];
    float* out = (float*)d_out;

    const int smem1 = (12608 + 8 * WARP_SLAB) * 4;   // 96512 B
    const int smem2 = 53760 * 4;                     // 215040 B
    cudaFuncSetAttribute(attn_kernel, cudaFuncAttributeMaxDynamicSharedMemorySize, smem1);
    cudaFuncSetAttribute(mlp_kernel,  cudaFuncAttributeMaxDynamicSharedMemorySize, smem2);

    attn_kernel<<<296, 256, smem1>>>(u, x, Wk, bk, Wq, bq, Wv, bv, g1, be1);
    mlp_kernel<<<148, 512, smem2>>>(x, Wm1, bm1, Wm2, bm2, g2, be2, Ws, bs, out);
}